// round 16
// baseline (speedup 1.0000x reference)
#include <cuda_runtime.h>
#include <cuda_fp16.h>
#include <cstdint>

// ---------------------------------------------------------------------------
// VersorLinear (Cl(4,1), 32-dim) via Cl(4,1) ~= M4(C):
//   Yhat[b,o] = sum_f Xhat[b,f] . What[o,f]  -> one real GEMM
//   [16384 x 1024 x 1024]  (4x fewer MACs than the direct 4096^3 GEMM).
// Round 13: kill the mainloop register spills. regs was pinned at the
// __launch_bounds__(256,2) 128-reg cap and ~2.7 GB of invariant DRAM
// traffic (= acc spill r/w) survived every epilogue change. Now:
//   - __launch_bounds__(256, 1): up to 255 regs, no spills
//   - occupancy 1 compensated by a 6-deep cp.async ring (221 KB smem,
//     prefetch distance 5; tail uses empty commit_groups)
// Mainloop math + slab layout + validated spill-free epilogue unchanged.
// ---------------------------------------------------------------------------

#define MDIM 4096
#define GM 16384      // (b, r)    = 4096*4
#define GK 1024       // (f, s, p) = 128*4*2
#define GN 1024       // (o, c, q) = 128*4*2
#define BKH 64        // k-tile in halfs (one slab column block)
#define KT (GK / BKH) // 16 slabs

#define SLAB_A ((size_t)GM * BKH)    // halfs per A slab
#define SLAB_B ((size_t)GN * BKH)

// Slab layouts: addr(m,k) = (k>>6)*SLAB + m*64 + (k&63)
__device__ __half g_Xt[(size_t)GM * GK];
__device__ __half g_Wt16[(size_t)GN * GK];
__device__ float  g_TF[32 * 32];   // [(r*8+s*2+p)][i] = part(R_i[r][s])
__device__ float  g_TI[32 * 32];   // [i][(r*4+c)*2+q] = part(R_i[r][c])/4

struct cpx { float re, im; };
__device__ __forceinline__ cpx cmul(cpx a, cpx b) {
    return { a.re * b.re - a.im * b.im, a.re * b.im + a.im * b.re };
}
__device__ void mm4(cpx* out, const cpx* A, const cpx* B) {
    for (int r = 0; r < 4; r++)
        for (int c = 0; c < 4; c++) {
            cpx s = {0.f, 0.f};
            for (int k = 0; k < 4; k++) {
                cpx p = cmul(A[r * 4 + k], B[k * 4 + c]);
                s.re += p.re; s.im += p.im;
            }
            out[r * 4 + c] = s;
        }
}

// One thread per blade a (32 threads): R_a = ordered gamma product.
__global__ void build_tables() {
    int a = threadIdx.x;
    if (a >= 32) return;
    cpx G[5][16];
    for (int m = 0; m < 5; m++)
        for (int e = 0; e < 16; e++) G[m][e] = {0.f, 0.f};
    G[0][0] = {1,0}; G[0][5] = {1,0}; G[0][10] = {-1,0}; G[0][15] = {-1,0};
    G[1][3] = {1,0}; G[1][6] = {1,0}; G[1][9] = {1,0}; G[1][12] = {1,0};
    G[2][3] = {0,-1}; G[2][6] = {0,1}; G[2][9] = {0,-1}; G[2][12] = {0,1};
    G[3][2] = {1,0}; G[3][7] = {-1,0}; G[3][8] = {1,0}; G[3][13] = {-1,0};
    {   // e4 = i * e0 e1 e2 e3
        cpx P[16], Q[16], T[16];
        mm4(P, G[0], G[1]);
        mm4(Q, G[2], G[3]);
        mm4(T, P, Q);
        for (int e = 0; e < 16; e++) G[4][e] = { -T[e].im, T[e].re };
    }
    cpx R[16], T[16];
    for (int e = 0; e < 16; e++) R[e] = {0.f, 0.f};
    R[0] = R[5] = R[10] = R[15] = {1.f, 0.f};
    for (int i = 0; i < 5; i++)
        if ((a >> i) & 1) {
            mm4(T, R, G[i]);
            for (int e = 0; e < 16; e++) R[e] = T[e];
        }
    for (int r = 0; r < 4; r++)
        for (int c = 0; c < 4; c++) {
            cpx v = R[r * 4 + c];
            g_TF[(r * 8 + c * 2 + 0) * 32 + a] = v.re;
            g_TF[(r * 8 + c * 2 + 1) * 32 + a] = v.im;
            g_TI[a * 32 + (r * 4 + c) * 2 + 0] = 0.25f * v.re;
            g_TI[a * 32 + (r * 4 + c) * 2 + 1] = 0.25f * v.im;
        }
}

// x[b,f,:] -> Xhat rows m=b*4+r written into slab layout.
__global__ void xform_x(const float* __restrict__ X) {
    __shared__ float TFs[1024];
    for (int i = threadIdx.x; i < 1024; i += 256) TFs[i] = g_TF[i];
    __syncthreads();

    int t = blockIdx.x * 256 + threadIdx.x;   // 0 .. 524287
    int b = t >> 7, f = t & 127;
    const float* xv = X + (size_t)b * 4096 + f * 32;
    float xr[32];
#pragma unroll
    for (int q = 0; q < 8; q++) {
        float4 v = *reinterpret_cast<const float4*>(xv + q * 4);
        xr[q * 4 + 0] = v.x; xr[q * 4 + 1] = v.y;
        xr[q * 4 + 2] = v.z; xr[q * 4 + 3] = v.w;
    }
    int kt = f >> 3, kk0 = (f & 7) * 8;
#pragma unroll
    for (int r = 0; r < 4; r++) {
        __half out[8];
#pragma unroll
        for (int sp = 0; sp < 8; sp++) {
            const float* row = &TFs[(r * 8 + sp) * 32];
            float a = 0.f;
#pragma unroll
            for (int i = 0; i < 32; i++) a += row[i] * xr[i];
            out[sp] = __float2half_rn(a);
        }
        size_t off = (size_t)kt * SLAB_A + (size_t)(b * 4 + r) * BKH + kk0;
        *reinterpret_cast<uint4*>(&g_Xt[off]) = *reinterpret_cast<const uint4*>(out);
    }
}

// w[o,f,:] -> What, realified [[Wr,Wi],[-Wi,Wr]], into slab layout.
__global__ void xform_w(const float* __restrict__ W) {
    __shared__ float TFs[1024];
    for (int i = threadIdx.x; i < 1024; i += 256) TFs[i] = g_TF[i];
    __syncthreads();

    int t = blockIdx.x * 256 + threadIdx.x;   // 0 .. 16383
    int o = t >> 7, f = t & 127;
    const float* wv = W + (size_t)o * 4096 + f * 32;
    float wr32[32];
#pragma unroll
    for (int q = 0; q < 8; q++) {
        float4 v = *reinterpret_cast<const float4*>(wv + q * 4);
        wr32[q * 4 + 0] = v.x; wr32[q * 4 + 1] = v.y;
        wr32[q * 4 + 2] = v.z; wr32[q * 4 + 3] = v.w;
    }
    int kt = f >> 3, kk0 = (f & 7) * 8;
#pragma unroll
    for (int s = 0; s < 4; s++)
#pragma unroll
        for (int c = 0; c < 4; c++) {
            float wr = 0.f, wi = 0.f;
#pragma unroll
            for (int j = 0; j < 32; j++) {
                wr += TFs[(s * 8 + c * 2 + 0) * 32 + j] * wr32[j];
                wi += TFs[(s * 8 + c * 2 + 1) * 32 + j] * wr32[j];
            }
            int kk = kk0 + s * 2;
            int n0 = o * 8 + c * 2;
            size_t base = (size_t)kt * SLAB_B;
            g_Wt16[base + (size_t)(n0 + 0) * BKH + kk + 0] = __float2half_rn(wr);
            g_Wt16[base + (size_t)(n0 + 0) * BKH + kk + 1] = __float2half_rn(-wi);
            g_Wt16[base + (size_t)(n0 + 1) * BKH + kk + 0] = __float2half_rn(wi);
            g_Wt16[base + (size_t)(n0 + 1) * BKH + kk + 1] = __float2half_rn(wr);
        }
}

// ---------------------------------------------------------------------------
#define BM 128
#define BN 128
#define NST 6
#define LDSD 72                          // smem row stride in HALFS (144 B)
#define STG_H (BM * LDSD)                // 9216 halfs per stage per matrix
#define SMEM_BYTES (NST * 2 * STG_H * 2) // 221184

#define CP_ASYNC16(smaddr, gptr) \
    asm volatile("cp.async.cg.shared.global [%0], [%1], 16;" :: "r"(smaddr), "l"(gptr))

__global__ __launch_bounds__(256, 1)
void gemm_tc_kernel(float* __restrict__ C) {
    extern __shared__ __half smem[];
    __half* As = smem;                    // [NST][BM][LDSD]
    __half* Bs = smem + NST * STG_H;
    uint32_t sAs = (uint32_t)__cvta_generic_to_shared(As);
    uint32_t sBs = (uint32_t)__cvta_generic_to_shared(Bs);

    const int tid  = threadIdx.x;
    const int lane = tid & 31;
    const int wid  = tid >> 5;
    const int warpM = wid >> 2;          // 0..1
    const int warpN = wid & 3;           // 0..3
    const int blockRow = blockIdx.y * BM;
    const int blockCol = blockIdx.x * BN;

#define LOAD_TILE(t, stage) do {                                               \
    const __half* _ga = g_Xt   + (size_t)(t) * SLAB_A + (size_t)blockRow * BKH;\
    const __half* _gb = g_Wt16 + (size_t)(t) * SLAB_B + (size_t)blockCol * BKH;\
    uint32_t _sa = sAs + (uint32_t)((stage) * STG_H) * 2u;                     \
    uint32_t _sb = sBs + (uint32_t)((stage) * STG_H) * 2u;                     \
    _Pragma("unroll")                                                          \
    for (int _i = 0; _i < 4; _i++) {                                           \
        int _j = tid + 256 * _i;                                               \
        CP_ASYNC16(_sa + (uint32_t)(((_j >> 3) * LDSD + (_j & 7) * 8) * 2),    \
                   _ga + (size_t)_j * 8);                                      \
    }                                                                          \
    _Pragma("unroll")                                                          \
    for (int _i = 0; _i < 4; _i++) {                                           \
        int _j = tid + 256 * _i;                                               \
        CP_ASYNC16(_sb + (uint32_t)(((_j >> 3) * LDSD + (_j & 7) * 8) * 2),    \
                   _gb + (size_t)_j * 8);                                      \
    }                                                                          \
    asm volatile("cp.async.commit_group;");                                    \
} while (0)

    float acc[4][4][4] = {};

    // preload NST-1 = 5 stages
    LOAD_TILE(0, 0);
    LOAD_TILE(1, 1);
    LOAD_TILE(2, 2);
    LOAD_TILE(3, 3);
    LOAD_TILE(4, 4);

    const int aRowBase = warpM * 64 + (lane >> 2);
    const int t2 = (lane & 3) * 2;
    const int bRowBase = warpN * 32 + (lane >> 2);

    for (int t = 0; t < KT; t++) {       // 16 iterations
        const int stage = t % NST;
        asm volatile("cp.async.wait_group %0;" :: "n"(NST - 2));
        __syncthreads();
        if (t + NST - 1 < KT) {
            LOAD_TILE(t + NST - 1, (t + NST - 1) % NST);
        } else {
            asm volatile("cp.async.commit_group;");   // keep group count exact
        }

        const __half* as = As + stage * STG_H + aRowBase * LDSD + t2;
        const __half* bs = Bs + stage * STG_H + bRowBase * LDSD + t2;

#pragma unroll
        for (int ks = 0; ks < 4; ks++) {             // four k16 slices in BK=64
            const int kof = ks * 16;
            uint32_t a[4][4], b[4][2];
#pragma unroll
            for (int mf = 0; mf < 4; mf++) {
                a[mf][0] = *reinterpret_cast<const uint32_t*>(&as[(mf * 16    ) * LDSD + kof    ]);
                a[mf][1] = *reinterpret_cast<const uint32_t*>(&as[(mf * 16 + 8) * LDSD + kof    ]);
                a[mf][2] = *reinterpret_cast<const uint32_t*>(&as[(mf * 16    ) * LDSD + kof + 8]);
                a[mf][3] = *reinterpret_cast<const uint32_t*>(&as[(mf * 16 + 8) * LDSD + kof + 8]);
            }
#pragma unroll
            for (int nf = 0; nf < 4; nf++) {
                b[nf][0] = *reinterpret_cast<const uint32_t*>(&bs[(nf * 8) * LDSD + kof    ]);
                b[nf][1] = *reinterpret_cast<const uint32_t*>(&bs[(nf * 8) * LDSD + kof + 8]);
            }
#pragma unroll
            for (int mf = 0; mf < 4; mf++)
#pragma unroll
                for (int nf = 0; nf < 4; nf++)
                    asm volatile(
                        "mma.sync.aligned.m16n8k16.row.col.f32.f16.f16.f32 "
                        "{%0,%1,%2,%3}, {%4,%5,%6,%7}, {%8,%9}, {%0,%1,%2,%3};"
                        : "+f"(acc[mf][nf][0]), "+f"(acc[mf][nf][1]),
                          "+f"(acc[mf][nf][2]), "+f"(acc[mf][nf][3])
                        : "r"(a[mf][0]), "r"(a[mf][1]), "r"(a[mf][2]), "r"(a[mf][3]),
                          "r"(b[nf][0]), "r"(b[nf][1]));
        }
    }

    // ---- fused epilogue, spill-free (validated rounds 10/12) ---------------
    float* S   = reinterpret_cast<float*>(smem);       // [32][520]
    float* TIs = S + 32 * 520;                         // 1024 floats
    __syncthreads();

    for (int idx = tid; idx < 1024; idx += 256) TIs[idx] = g_TI[idx];

#pragma unroll
    for (int mf = 0; mf < 4; mf++)
#pragma unroll
        for (int nf = 0; nf < 4; nf++)
#pragma unroll
            for (int cc = 0; cc < 4; cc++) {
                int ml = warpM * 64 + mf * 16 + (lane >> 2) + ((cc >> 1) ? 8 : 0);
                int nl = warpN * 32 + nf * 8 + (lane & 3) * 2 + (cc & 1);
                int e = (ml & 3) * 8 + (nl & 7);
                int g = (ml >> 2) * 16 + (nl >> 3);
                S[e * 520 + g] = acc[mf][nf][cc];
            }
    __syncthreads();

    // Norm via TI orthogonality: sum_i y_i^2 = 0.25 * sum_e v_e^2.
    for (int g = tid; g < 512; g += 256) {
        float ssum = 0.f;
#pragma unroll
        for (int e = 0; e < 32; e++) {
            float ve = S[e * 520 + g];
            ssum += ve * ve;
        }
        float inv = rsqrtf(0.25f * ssum + 1e-6f);

        int b_l = g >> 4, o_l = g & 15;
        float* crow = C + ((size_t)(blockIdx.y * 32 + b_l)) * 4096
                        + (size_t)(blockIdx.x * 16 + o_l) * 32;
#pragma unroll
        for (int i4 = 0; i4 < 8; i4++) {
            float o0 = 0.f, o1 = 0.f, o2 = 0.f, o3 = 0.f;
#pragma unroll
            for (int e = 0; e < 32; e++) {
                float ve = S[e * 520 + g];
                o0 += TIs[(i4 * 4 + 0) * 32 + e] * ve;
                o1 += TIs[(i4 * 4 + 1) * 32 + e] * ve;
                o2 += TIs[(i4 * 4 + 2) * 32 + e] * ve;
                o3 += TIs[(i4 * 4 + 3) * 32 + e] * ve;
            }
            float4 o4 = make_float4(o0 * inv, o1 * inv, o2 * inv, o3 * inv);
            *reinterpret_cast<float4*>(crow + i4 * 4) = o4;
        }
    }
}

// ---------------------------------------------------------------------------
extern "C" void kernel_launch(void* const* d_in, const int* in_sizes, int n_in,
                              void* d_out, int out_size) {
    const float* x = (const float*)d_in[0];
    const float* w = (const float*)d_in[1];
    if (n_in >= 2 && in_sizes[0] == 524288 && in_sizes[1] == 16777216) {
        const float* t = x; x = w; w = t;  // defensive order swap
    }
    float* y = (float*)d_out;

    build_tables<<<1, 32>>>();
    xform_x<<<2048, 256>>>(x);
    xform_w<<<64, 256>>>(w);

    cudaFuncSetAttribute(gemm_tc_kernel,
                         cudaFuncAttributeMaxDynamicSharedMemorySize, SMEM_BYTES);
    dim3 grid(GN / BN, GM / BM);  // 8 x 128
    gemm_tc_kernel<<<grid, 256, SMEM_BYTES>>>(y);
}